// round 1
// baseline (speedup 1.0000x reference)
#include <cuda_runtime.h>
#include <math.h>
#include <stdint.h>

#define NN   50000
#define DD   96
#define EE   800000
#define GG   2048
#define LL   64
#define HH   8
#define D2   192
#define EPSV 0.3f
#define QSCALE 0.2886751345948129f  // 1/sqrt(12)

// ---------------- device scratch (no allocations allowed) ----------------
__device__ int    g_deg[NN];
__device__ float4 g_pack[NN];          // (gl, gr, dinv, _) per node
__device__ float  g_buf1[NN*DD];       // layer-1 accumulator
__device__ float  g_buf2[NN*DD];       // layer-2 input (relu of layer-1 out)
__device__ float  g_S[NN*DD];
__device__ float  g_A[NN*DD];
__device__ float  g_B[NN*DD];
__device__ float  g_CAT[NN*D2];
__device__ float  g_H[NN*DD];
__device__ float  g_KN[NN*DD];
__device__ float  g_VN[NN*DD];
__device__ float  g_WtLin[D2*DD];      // [k][j] = w_lin[j][k]
__device__ float  g_WtKV[DD*D2];       // [c][r] = w_qkv[96+r][c]
__device__ float  g_WtQ[DD*DD];        // [c][j] = w_qkv[j][c]
__device__ float  g_WtO[DD*DD];        // [c][j] = w_o[j][c]

// ---------------- small helpers ----------------
__device__ __forceinline__ float warp_sum(float v) {
    #pragma unroll
    for (int o = 16; o > 0; o >>= 1) v += __shfl_xor_sync(0xffffffffu, v, o);
    return v;
}

__device__ __forceinline__ void red_add_v4(float* p, float4 v) {
    asm volatile("red.global.add.v4.f32 [%0], {%1,%2,%3,%4};"
                 :: "l"(p), "f"(v.x), "f"(v.y), "f"(v.z), "f"(v.w) : "memory");
}

// ---------------- kernels ----------------
__global__ void k_zero_deg() {
    int i = blockIdx.x * blockDim.x + threadIdx.x;
    if (i < NN) g_deg[i] = 0;
}

__global__ void k_count(const int* __restrict__ edges) {
    int e = blockIdx.x * blockDim.x + threadIdx.x;
    if (e < EE) atomicAdd(&g_deg[edges[e]], 1);  // row = edges[0][e]
}

// warp per node: compute layer input y (relu of prev acc if accin!=null),
// gl = y.al, gr = y.ar; init acc target = EPS * raw x; write pack(gl,gr,dinv).
__global__ void k_prep(const float* __restrict__ raw,
                       const float* __restrict__ accin,
                       float* __restrict__ ysto,
                       const float* __restrict__ al,
                       const float* __restrict__ ar,
                       float* __restrict__ initbuf) {
    int w = (blockIdx.x * blockDim.x + threadIdx.x) >> 5;
    int lane = threadIdx.x & 31;
    if (w >= NN) return;
    int base = w * DD;
    float gl = 0.f, gr = 0.f;
    #pragma unroll
    for (int i = 0; i < 3; i++) {
        int d = lane + 32 * i;
        float rv = raw[base + d];
        float y;
        if (accin) {
            y = fmaxf(accin[base + d], 0.f);
            ysto[base + d] = y;
        } else {
            y = rv;
        }
        gl += y * al[d];
        gr += y * ar[d];
        initbuf[base + d] = EPSV * rv;
    }
    gl = warp_sum(gl);
    gr = warp_sum(gr);
    if (lane == 0) {
        int dg = g_deg[w];
        float dinv = dg > 0 ? rsqrtf((float)dg) : 0.f;
        g_pack[w] = make_float4(gl, gr, dinv, 0.f);
    }
}

// warp per edge: coef = tanh(gl[row]+gr[col])*dinv[row]*dinv[col];
// acc[row] += coef * xsrc[col]  via red.v4
__global__ void k_edge(const int* __restrict__ edges,
                       const float* __restrict__ xsrc,
                       float* __restrict__ acc) {
    int w = (blockIdx.x * blockDim.x + threadIdx.x) >> 5;
    int lane = threadIdx.x & 31;
    if (w >= EE) return;
    int row = edges[w];
    int col = edges[EE + w];
    float4 pr = g_pack[row];
    float4 pc = g_pack[col];
    float coef = tanhf(pr.x + pc.y) * pr.z * pc.z;
    if (coef != 0.f && lane < 24) {
        float4 xv = reinterpret_cast<const float4*>(xsrc)[col * 24 + lane];
        xv.x *= coef; xv.y *= coef; xv.z *= coef; xv.w *= coef;
        red_add_v4(acc + row * DD + lane * 4, xv);
    }
}

// warp per node: gating softmaxes + build cat = [ga_out, gb_out]
__global__ void k_combine(const float* __restrict__ x,
                          const float* __restrict__ wga,
                          const float* __restrict__ bga,
                          const float* __restrict__ wgb,
                          const float* __restrict__ bgb) {
    int n = (blockIdx.x * blockDim.x + threadIdx.x) >> 5;
    int lane = threadIdx.x & 31;
    if (n >= NN) return;
    int base = n * DD;
    float l0 = 0.f, l1 = 0.f, m0 = 0.f, m1 = 0.f;
    float sv[3], av[3], bv[3];
    #pragma unroll
    for (int i = 0; i < 3; i++) {
        int d = lane + 32 * i;
        float xx = x[base + d];
        l0 += xx * wga[d];
        l1 += xx * wga[DD + d];
        m0 += xx * wgb[d];
        m1 += xx * wgb[DD + d];
        sv[i] = fmaxf(g_S[base + d], 0.f);
        av[i] = fmaxf(g_A[base + d], 0.f);
        bv[i] = fmaxf(g_B[base + d], 0.f);
    }
    l0 = warp_sum(l0); l1 = warp_sum(l1);
    m0 = warp_sum(m0); m1 = warp_sum(m1);
    l0 += bga[0]; l1 += bga[1];
    m0 += bgb[0]; m1 += bgb[1];
    float ga0 = 1.f / (1.f + __expf(l1 - l0));
    float ga1 = 1.f - ga0;
    float gb0 = 1.f / (1.f + __expf(m1 - m0));
    float gb1 = 1.f - gb0;
    #pragma unroll
    for (int i = 0; i < 3; i++) {
        int d = lane + 32 * i;
        g_CAT[n * D2 + d]      = ga0 * av[i] + ga1 * sv[i];
        g_CAT[n * D2 + DD + d] = gb0 * bv[i] + gb1 * sv[i];
    }
}

__global__ void k_transpose(const float* __restrict__ w_lin,
                            const float* __restrict__ w_qkv,
                            const float* __restrict__ w_o) {
    int t = blockIdx.x * blockDim.x + threadIdx.x;
    if (t >= D2 * DD) return;
    {   // WtLin: [k][j]
        int k = t / DD, j = t % DD;
        g_WtLin[t] = w_lin[j * D2 + k];
    }
    {   // WtKV: [c][r], r in [0,192): rows 96..287 of w_qkv
        int c = t / D2, r = t % D2;
        g_WtKV[t] = w_qkv[(DD + r) * DD + c];
    }
    if (t < DD * DD) {
        int c = t / DD, j = t % DD;
        g_WtQ[t] = w_qkv[j * DD + c];
        g_WtO[t] = w_o[j * DD + c];
    }
}

// h = relu(CAT @ w_lin^T + b_lin): block = 96 threads (j), 32 nodes per block
__global__ void k_gemm_h(const float* __restrict__ b_lin) {
    __shared__ float As[32 * D2];
    int j = threadIdx.x;          // 0..95
    int base = blockIdx.x * 32;
    int cnt = min(32, NN - base);
    for (int idx = j; idx < cnt * D2; idx += DD) {
        int r = idx / D2, c = idx % D2;
        As[r * D2 + c] = g_CAT[(base + r) * D2 + c];
    }
    __syncthreads();
    float acc[32];
    #pragma unroll
    for (int m = 0; m < 32; m++) acc[m] = 0.f;
    const float4* As4 = reinterpret_cast<const float4*>(As);
    #pragma unroll 4
    for (int k4 = 0; k4 < D2 / 4; k4++) {
        int k = k4 * 4;
        float w0 = g_WtLin[(k + 0) * DD + j];
        float w1 = g_WtLin[(k + 1) * DD + j];
        float w2 = g_WtLin[(k + 2) * DD + j];
        float w3 = g_WtLin[(k + 3) * DD + j];
        #pragma unroll
        for (int m = 0; m < 32; m++) {
            float4 a = As4[m * (D2 / 4) + k4];
            acc[m] += a.x * w0 + a.y * w1 + a.z * w2 + a.w * w3;
        }
    }
    float bj = b_lin[j];
    for (int m = 0; m < cnt; m++)
        g_H[(base + m) * DD + j] = fmaxf(acc[m] + bj, 0.f);
}

// K,V per node: block = 192 threads (j), 32 nodes per block
__global__ void k_gemm_kv(const float* __restrict__ b_qkv) {
    __shared__ float As[32 * DD];
    int j = threadIdx.x;          // 0..191
    int base = blockIdx.x * 32;
    int cnt = min(32, NN - base);
    for (int idx = j; idx < cnt * DD; idx += D2) {
        int r = idx / DD, c = idx % DD;
        As[r * DD + c] = g_H[(base + r) * DD + c];
    }
    __syncthreads();
    float acc[32];
    #pragma unroll
    for (int m = 0; m < 32; m++) acc[m] = 0.f;
    const float4* As4 = reinterpret_cast<const float4*>(As);
    #pragma unroll 4
    for (int k4 = 0; k4 < DD / 4; k4++) {
        int k = k4 * 4;
        float w0 = g_WtKV[(k + 0) * D2 + j];
        float w1 = g_WtKV[(k + 1) * D2 + j];
        float w2 = g_WtKV[(k + 2) * D2 + j];
        float w3 = g_WtKV[(k + 3) * D2 + j];
        #pragma unroll
        for (int m = 0; m < 32; m++) {
            float4 a = As4[m * (DD / 4) + k4];
            acc[m] += a.x * w0 + a.y * w1 + a.z * w2 + a.w * w3;
        }
    }
    float bj = b_qkv[DD + j];
    if (j < DD) {
        for (int m = 0; m < cnt; m++)
            g_KN[(base + m) * DD + j] = acc[m] + bj;
    } else {
        int jj = j - DD;
        for (int m = 0; m < cnt; m++)
            g_VN[(base + m) * DD + jj] = acc[m] + bj;
    }
}

// attention: block per group (128 threads); only row l=0 is needed.
__global__ void k_attn(const int* __restrict__ target_ids,
                       const int* __restrict__ target_lens,
                       const float* __restrict__ b_qkv,
                       const float* __restrict__ b_o,
                       float* __restrict__ out) {
    __shared__ int   sn[LL];
    __shared__ int   slen;
    __shared__ float hrow[DD];
    __shared__ float qs[DD];
    __shared__ float Ks[LL * 97];
    __shared__ float sc[HH * 68];
    __shared__ float cs[DD];

    int g = blockIdx.x;
    int tid = threadIdx.x;

    if (tid < LL) sn[tid] = target_ids[g * LL + tid];
    if (tid == 64) slen = target_lens[g];
    __syncthreads();

    if (tid < DD) hrow[tid] = g_H[sn[0] * DD + tid];
    __syncthreads();

    // stage K rows (gathered by node) + compute q for token 0
    for (int idx = tid; idx < LL * DD; idx += blockDim.x) {
        int m = idx / DD, c = idx % DD;
        Ks[m * 97 + c] = g_KN[sn[m] * DD + c];
    }
    if (tid < DD) {
        float s = 0.f;
        #pragma unroll 8
        for (int c = 0; c < DD; c++) s += hrow[c] * g_WtQ[c * DD + tid];
        qs[tid] = (s + b_qkv[tid]) * QSCALE;
    }
    __syncthreads();

    int len = slen;
    // scores for valid m only
    if (tid < LL && tid < len) {
        int m = tid;
        const float* kr = &Ks[m * 97];
        #pragma unroll
        for (int h = 0; h < HH; h++) {
            float s = 0.f;
            #pragma unroll
            for (int d = 0; d < 12; d++) s += qs[h * 12 + d] * kr[h * 12 + d];
            sc[h * 68 + m] = s;
        }
    }
    __syncthreads();

    // per-head softmax over m < len (serial per head; tiny)
    if (tid < HH) {
        float* row = &sc[tid * 68];
        float mx = row[0];
        for (int m = 1; m < len; m++) mx = fmaxf(mx, row[m]);
        float sum = 0.f;
        for (int m = 0; m < len; m++) {
            float e = __expf(row[m] - mx);
            row[m] = e;
            sum += e;
        }
        float inv = 1.f / sum;
        for (int m = 0; m < len; m++) row[m] *= inv;
    }
    __syncthreads();

    // weights output: mean over heads at l=0
    if (tid < LL) {
        float wv = 0.f;
        if (tid < len) {
            #pragma unroll
            for (int h = 0; h < HH; h++) wv += sc[h * 68 + tid];
            wv *= (1.f / HH);
        }
        out[GG * DD + g * LL + tid] = wv;
    }
    // ctx row 0
    if (tid < DD) {
        int h = tid / 12;
        float a = 0.f;
        for (int m = 0; m < len; m++)
            a += sc[h * 68 + m] * g_VN[sn[m] * DD + tid];
        cs[tid] = a;
    }
    __syncthreads();

    // out = ctx @ w_o^T + b_o
    if (tid < DD) {
        float o = b_o[tid];
        #pragma unroll 8
        for (int c = 0; c < DD; c++) o += cs[c] * g_WtO[c * DD + tid];
        out[g * DD + tid] = o;
    }
}

// ---------------- launch ----------------
extern "C" void kernel_launch(void* const* d_in, const int* in_sizes, int n_in,
                              void* d_out, int out_size) {
    const float* x     = (const float*)d_in[0];
    const float* a_l   = (const float*)d_in[1];
    const float* a_r   = (const float*)d_in[2];
    const float* w_ga  = (const float*)d_in[3];
    const float* b_ga  = (const float*)d_in[4];
    const float* w_gb  = (const float*)d_in[5];
    const float* b_gb  = (const float*)d_in[6];
    const float* w_lin = (const float*)d_in[7];
    const float* b_lin = (const float*)d_in[8];
    const float* w_qkv = (const float*)d_in[9];
    const float* b_qkv = (const float*)d_in[10];
    const float* w_o   = (const float*)d_in[11];
    const float* b_o   = (const float*)d_in[12];
    const int*   grph[3] = {(const int*)d_in[13], (const int*)d_in[14], (const int*)d_in[15]};
    const int*   target_ids  = (const int*)d_in[16];
    const int*   target_lens = (const int*)d_in[17];
    float* out = (float*)d_out;

    float *pb1, *pb2, *pS, *pA, *pB;
    cudaGetSymbolAddress((void**)&pb1, g_buf1);
    cudaGetSymbolAddress((void**)&pb2, g_buf2);
    cudaGetSymbolAddress((void**)&pS,  g_S);
    cudaGetSymbolAddress((void**)&pA,  g_A);
    cudaGetSymbolAddress((void**)&pB,  g_B);
    float* outs[3] = {pS, pA, pB};   // g0->s_out, g1->a_out, g2->b_out

    const int nodeBlocks = (NN + 7) / 8;    // warp per node, 256 thr
    const int edgeBlocks = (EE + 7) / 8;    // warp per edge, 256 thr

    k_transpose<<<(D2 * DD + 255) / 256, 256>>>(w_lin, w_qkv, w_o);

    for (int i = 0; i < 3; i++) {
        k_zero_deg<<<(NN + 255) / 256, 256>>>();
        k_count<<<(EE + 255) / 256, 256>>>(grph[i]);
        // layer 1: input x, x0 = x, acc -> g_buf1
        k_prep<<<nodeBlocks, 256>>>(x, nullptr, nullptr, a_l, a_r, pb1);
        k_edge<<<edgeBlocks, 256>>>(grph[i], x, pb1);
        // layer 2: input relu(buf1) -> buf2, x0 = x, acc -> outs[i]
        k_prep<<<nodeBlocks, 256>>>(x, pb1, pb2, a_l + DD, a_r + DD, outs[i]);
        k_edge<<<edgeBlocks, 256>>>(grph[i], pb2, outs[i]);
    }

    k_combine<<<nodeBlocks, 256>>>(x, w_ga, b_ga, w_gb, b_gb);
    k_gemm_h<<<(NN + 31) / 32, DD>>>(b_lin);
    k_gemm_kv<<<(NN + 31) / 32, D2>>>(b_qkv);
    k_attn<<<GG, 128>>>(target_ids, target_lens, b_qkv, b_o, out);
}

// round 3
// speedup vs baseline: 1.1375x; 1.1375x over previous
#include <cuda_runtime.h>
#include <math.h>
#include <stdint.h>

#define NN   50000
#define DD   96
#define EE   800000
#define GG   2048
#define LL   64
#define HH   8
#define D2   192
#define EPSV 0.3f
#define QSCALE 0.2886751345948129f  // 1/sqrt(12)

// ---------------- device scratch (no allocations allowed) ----------------
__device__ int    g_deg[NN];
__device__ int    g_offs[NN + 1];
__device__ int    g_cur[NN];
__device__ int    g_col[EE];
__device__ float  g_dinv[NN];
__device__ float2 g_glr1[NN];          // (gl, gr) for layer-1 input x (graph-independent)
__device__ float2 g_glr2[NN];          // (gl, gr) for layer-2 input y (per-graph, reused)
__device__ float  g_Y[NN*DD];          // relu(layer-1 out), per-graph reused
__device__ float  g_S[NN*DD];
__device__ float  g_A[NN*DD];
__device__ float  g_B[NN*DD];
__device__ float  g_CAT[NN*D2];
__device__ float  g_H[NN*DD];
__device__ float  g_KN[NN*DD];
__device__ float  g_VN[NN*DD];
__device__ float  g_WtLin[D2*DD];      // [k][j] = w_lin[j][k]
__device__ float  g_WtKV[DD*D2];       // [c][r] = w_qkv[96+r][c]
__device__ float  g_WtQ[DD*DD];        // [c][j] = w_qkv[j][c]
__device__ float  g_WtO[DD*DD];        // [c][j] = w_o[j][c]

// ---------------- small helpers ----------------
__device__ __forceinline__ float warp_sum(float v) {
    #pragma unroll
    for (int o = 16; o > 0; o >>= 1) v += __shfl_xor_sync(0xffffffffu, v, o);
    return v;
}

// ---------------- CSR construction ----------------
__global__ void k_zero_deg() {
    int i = blockIdx.x * blockDim.x + threadIdx.x;
    if (i < NN) g_deg[i] = 0;
}

__global__ void k_count(const int* __restrict__ edges) {
    int e = blockIdx.x * blockDim.x + threadIdx.x;
    if (e < EE) atomicAdd(&g_deg[edges[e]], 1);  // row = edges[0][e]
}

// single-block exclusive scan of g_deg -> g_offs, g_cur; also dinv.
__global__ void k_scan() {
    __shared__ int sh[1024];
    const int CH = (NN + 1023) / 1024;  // 49
    int tid = threadIdx.x;
    int begin = tid * CH;
    int end = min(begin + CH, NN);
    int sum = 0;
    for (int i = begin; i < end; i++) sum += g_deg[i];
    sh[tid] = sum;
    __syncthreads();
    for (int off = 1; off < 1024; off <<= 1) {
        int v = (tid >= off) ? sh[tid - off] : 0;
        __syncthreads();
        sh[tid] += v;
        __syncthreads();
    }
    int run = sh[tid] - sum;  // exclusive
    for (int i = begin; i < end; i++) {
        g_offs[i] = run;
        g_cur[i]  = run;
        int d = g_deg[i];
        g_dinv[i] = (d > 0) ? rsqrtf((float)d) : 0.f;
        run += d;
    }
    if (tid == 1023) g_offs[NN] = run;
}

__global__ void k_fill(const int* __restrict__ edges) {
    int e = blockIdx.x * blockDim.x + threadIdx.x;
    if (e >= EE) return;
    int row = edges[e];
    int col = edges[EE + e];
    int pos = atomicAdd(&g_cur[row], 1);
    g_col[pos] = col;
}

// ---------------- gl/gr for layer-1 input (x), computed once ----------------
__global__ void k_glr1(const float* __restrict__ x,
                       const float* __restrict__ al,
                       const float* __restrict__ ar) {
    int n = (blockIdx.x * blockDim.x + threadIdx.x) >> 5;
    int lane = threadIdx.x & 31;
    if (n >= NN) return;
    int base = n * DD;
    float gl = 0.f, gr = 0.f;
    #pragma unroll
    for (int i = 0; i < 3; i++) {
        int d = lane + 32 * i;
        float y = x[base + d];
        gl += y * al[d];
        gr += y * ar[d];
    }
    gl = warp_sum(gl);
    gr = warp_sum(gr);
    if (lane == 0) g_glr1[n] = make_float2(gl, gr);
}

// ---------------- layer-1 gather: acc = EPS*x + sum coef*x[col]; epilogue:
// y = relu(acc) -> g_Y, and glr2 = (y.al2, y.ar2) -> g_glr2
__global__ void k_gather1(const float* __restrict__ x,
                          const float* __restrict__ al2,
                          const float* __restrict__ ar2) {
    int n = (blockIdx.x * blockDim.x + threadIdx.x) >> 5;
    int lane = threadIdx.x & 31;
    if (n >= NN) return;
    int d0 = lane, d1 = lane + 32, d2 = lane + 64;
    float glrow = g_glr1[n].x;
    float dvrow = g_dinv[n];
    const float* xr = x + n * DD;
    float a0 = EPSV * xr[d0], a1 = EPSV * xr[d1], a2 = EPSV * xr[d2];
    int s = g_offs[n], e = g_offs[n + 1];
    for (int base = s; base < e; base += 32) {
        int idx = base + lane;
        int col = 0; float coef = 0.f;
        if (idx < e) {
            col = g_col[idx];
            float grc = g_glr1[col].y;
            coef = tanhf(glrow + grc) * dvrow * g_dinv[col];
        }
        int cnt = min(32, e - base);
        #pragma unroll 4
        for (int k = 0; k < cnt; k++) {
            int   c  = __shfl_sync(0xffffffffu, col, k);
            float cf = __shfl_sync(0xffffffffu, coef, k);
            const float* xc = x + c * DD;
            a0 = fmaf(cf, xc[d0], a0);
            a1 = fmaf(cf, xc[d1], a1);
            a2 = fmaf(cf, xc[d2], a2);
        }
    }
    a0 = fmaxf(a0, 0.f); a1 = fmaxf(a1, 0.f); a2 = fmaxf(a2, 0.f);
    g_Y[n * DD + d0] = a0;
    g_Y[n * DD + d1] = a1;
    g_Y[n * DD + d2] = a2;
    float gl = a0 * al2[d0] + a1 * al2[d1] + a2 * al2[d2];
    float gr = a0 * ar2[d0] + a1 * ar2[d1] + a2 * ar2[d2];
    gl = warp_sum(gl);
    gr = warp_sum(gr);
    if (lane == 0) g_glr2[n] = make_float2(gl, gr);
}

// ---------------- layer-2 gather: out = EPS*x + sum coef2*Y[col] ----------------
__global__ void k_gather2(const float* __restrict__ x,
                          float* __restrict__ outbuf) {
    int n = (blockIdx.x * blockDim.x + threadIdx.x) >> 5;
    int lane = threadIdx.x & 31;
    if (n >= NN) return;
    int d0 = lane, d1 = lane + 32, d2 = lane + 64;
    float glrow = g_glr2[n].x;
    float dvrow = g_dinv[n];
    const float* xr = x + n * DD;
    float a0 = EPSV * xr[d0], a1 = EPSV * xr[d1], a2 = EPSV * xr[d2];
    int s = g_offs[n], e = g_offs[n + 1];
    for (int base = s; base < e; base += 32) {
        int idx = base + lane;
        int col = 0; float coef = 0.f;
        if (idx < e) {
            col = g_col[idx];
            float grc = g_glr2[col].y;
            coef = tanhf(glrow + grc) * dvrow * g_dinv[col];
        }
        int cnt = min(32, e - base);
        #pragma unroll 4
        for (int k = 0; k < cnt; k++) {
            int   c  = __shfl_sync(0xffffffffu, col, k);
            float cf = __shfl_sync(0xffffffffu, coef, k);
            const float* yc = g_Y + c * DD;
            a0 = fmaf(cf, yc[d0], a0);
            a1 = fmaf(cf, yc[d1], a1);
            a2 = fmaf(cf, yc[d2], a2);
        }
    }
    outbuf[n * DD + d0] = a0;
    outbuf[n * DD + d1] = a1;
    outbuf[n * DD + d2] = a2;
}

// ---------------- gating + concat ----------------
__global__ void k_combine(const float* __restrict__ x,
                          const float* __restrict__ wga,
                          const float* __restrict__ bga,
                          const float* __restrict__ wgb,
                          const float* __restrict__ bgb) {
    int n = (blockIdx.x * blockDim.x + threadIdx.x) >> 5;
    int lane = threadIdx.x & 31;
    if (n >= NN) return;
    int base = n * DD;
    float l0 = 0.f, l1 = 0.f, m0 = 0.f, m1 = 0.f;
    float sv[3], av[3], bv[3];
    #pragma unroll
    for (int i = 0; i < 3; i++) {
        int d = lane + 32 * i;
        float xx = x[base + d];
        l0 += xx * wga[d];
        l1 += xx * wga[DD + d];
        m0 += xx * wgb[d];
        m1 += xx * wgb[DD + d];
        sv[i] = fmaxf(g_S[base + d], 0.f);
        av[i] = fmaxf(g_A[base + d], 0.f);
        bv[i] = fmaxf(g_B[base + d], 0.f);
    }
    l0 = warp_sum(l0); l1 = warp_sum(l1);
    m0 = warp_sum(m0); m1 = warp_sum(m1);
    l0 += bga[0]; l1 += bga[1];
    m0 += bgb[0]; m1 += bgb[1];
    float ga0 = 1.f / (1.f + __expf(l1 - l0));
    float ga1 = 1.f - ga0;
    float gb0 = 1.f / (1.f + __expf(m1 - m0));
    float gb1 = 1.f - gb0;
    #pragma unroll
    for (int i = 0; i < 3; i++) {
        int d = lane + 32 * i;
        g_CAT[n * D2 + d]      = ga0 * av[i] + ga1 * sv[i];
        g_CAT[n * D2 + DD + d] = gb0 * bv[i] + gb1 * sv[i];
    }
}

__global__ void k_transpose(const float* __restrict__ w_lin,
                            const float* __restrict__ w_qkv,
                            const float* __restrict__ w_o) {
    int t = blockIdx.x * blockDim.x + threadIdx.x;
    if (t >= D2 * DD) return;
    {   // WtLin: [k][j]
        int k = t / DD, j = t % DD;
        g_WtLin[t] = w_lin[j * D2 + k];
    }
    {   // WtKV: [c][r], r in [0,192): rows 96..287 of w_qkv
        int c = t / D2, r = t % D2;
        g_WtKV[t] = w_qkv[(DD + r) * DD + c];
    }
    if (t < DD * DD) {
        int c = t / DD, j = t % DD;
        g_WtQ[t] = w_qkv[j * DD + c];
        g_WtO[t] = w_o[j * DD + c];
    }
}

// h = relu(CAT @ w_lin^T + b_lin): block = 96 threads (j), 32 nodes per block
__global__ void k_gemm_h(const float* __restrict__ b_lin) {
    __shared__ float As[32 * D2];
    int j = threadIdx.x;          // 0..95
    int base = blockIdx.x * 32;
    int cnt = min(32, NN - base);
    for (int idx = j; idx < cnt * D2; idx += DD) {
        int r = idx / D2, c = idx % D2;
        As[r * D2 + c] = g_CAT[(base + r) * D2 + c];
    }
    __syncthreads();
    float acc[32];
    #pragma unroll
    for (int m = 0; m < 32; m++) acc[m] = 0.f;
    const float4* As4 = reinterpret_cast<const float4*>(As);
    #pragma unroll 4
    for (int k4 = 0; k4 < D2 / 4; k4++) {
        int k = k4 * 4;
        float w0 = g_WtLin[(k + 0) * DD + j];
        float w1 = g_WtLin[(k + 1) * DD + j];
        float w2 = g_WtLin[(k + 2) * DD + j];
        float w3 = g_WtLin[(k + 3) * DD + j];
        #pragma unroll
        for (int m = 0; m < 32; m++) {
            float4 a = As4[m * (D2 / 4) + k4];
            acc[m] += a.x * w0 + a.y * w1 + a.z * w2 + a.w * w3;
        }
    }
    float bj = b_lin[j];
    for (int m = 0; m < cnt; m++)
        g_H[(base + m) * DD + j] = fmaxf(acc[m] + bj, 0.f);
}

// K,V per node: block = 192 threads (j), 32 nodes per block
__global__ void k_gemm_kv(const float* __restrict__ b_qkv) {
    __shared__ float As[32 * DD];
    int j = threadIdx.x;          // 0..191
    int base = blockIdx.x * 32;
    int cnt = min(32, NN - base);
    for (int idx = j; idx < cnt * DD; idx += D2) {
        int r = idx / DD, c = idx % DD;
        As[r * DD + c] = g_H[(base + r) * DD + c];
    }
    __syncthreads();
    float acc[32];
    #pragma unroll
    for (int m = 0; m < 32; m++) acc[m] = 0.f;
    const float4* As4 = reinterpret_cast<const float4*>(As);
    #pragma unroll 4
    for (int k4 = 0; k4 < DD / 4; k4++) {
        int k = k4 * 4;
        float w0 = g_WtKV[(k + 0) * D2 + j];
        float w1 = g_WtKV[(k + 1) * D2 + j];
        float w2 = g_WtKV[(k + 2) * D2 + j];
        float w3 = g_WtKV[(k + 3) * D2 + j];
        #pragma unroll
        for (int m = 0; m < 32; m++) {
            float4 a = As4[m * (DD / 4) + k4];
            acc[m] += a.x * w0 + a.y * w1 + a.z * w2 + a.w * w3;
        }
    }
    float bj = b_qkv[DD + j];
    if (j < DD) {
        for (int m = 0; m < cnt; m++)
            g_KN[(base + m) * DD + j] = acc[m] + bj;
    } else {
        int jj = j - DD;
        for (int m = 0; m < cnt; m++)
            g_VN[(base + m) * DD + jj] = acc[m] + bj;
    }
}

// attention: block per group (128 threads); only row l=0 is needed.
__global__ void k_attn(const int* __restrict__ target_ids,
                       const int* __restrict__ target_lens,
                       const float* __restrict__ b_qkv,
                       const float* __restrict__ b_o,
                       float* __restrict__ out) {
    __shared__ int   sn[LL];
    __shared__ int   slen;
    __shared__ float hrow[DD];
    __shared__ float qs[DD];
    __shared__ float Ks[LL * 97];
    __shared__ float sc[HH * 68];
    __shared__ float cs[DD];

    int g = blockIdx.x;
    int tid = threadIdx.x;

    if (tid < LL) sn[tid] = target_ids[g * LL + tid];
    if (tid == 64) slen = target_lens[g];
    __syncthreads();

    if (tid < DD) hrow[tid] = g_H[sn[0] * DD + tid];
    __syncthreads();

    // stage K rows (gathered by node) + compute q for token 0
    for (int idx = tid; idx < LL * DD; idx += blockDim.x) {
        int m = idx / DD, c = idx % DD;
        Ks[m * 97 + c] = g_KN[sn[m] * DD + c];
    }
    if (tid < DD) {
        float s = 0.f;
        #pragma unroll 8
        for (int c = 0; c < DD; c++) s += hrow[c] * g_WtQ[c * DD + tid];
        qs[tid] = (s + b_qkv[tid]) * QSCALE;
    }
    __syncthreads();

    int len = slen;
    // scores for valid m only
    if (tid < LL && tid < len) {
        int m = tid;
        const float* kr = &Ks[m * 97];
        #pragma unroll
        for (int h = 0; h < HH; h++) {
            float s = 0.f;
            #pragma unroll
            for (int d = 0; d < 12; d++) s += qs[h * 12 + d] * kr[h * 12 + d];
            sc[h * 68 + m] = s;
        }
    }
    __syncthreads();

    // per-head softmax over m < len (serial per head; tiny)
    if (tid < HH) {
        float* row = &sc[tid * 68];
        float mx = row[0];
        for (int m = 1; m < len; m++) mx = fmaxf(mx, row[m]);
        float sum = 0.f;
        for (int m = 0; m < len; m++) {
            float e = __expf(row[m] - mx);
            row[m] = e;
            sum += e;
        }
        float inv = 1.f / sum;
        for (int m = 0; m < len; m++) row[m] *= inv;
    }
    __syncthreads();

    // weights output: mean over heads at l=0
    if (tid < LL) {
        float wv = 0.f;
        if (tid < len) {
            #pragma unroll
            for (int h = 0; h < HH; h++) wv += sc[h * 68 + tid];
            wv *= (1.f / HH);
        }
        out[GG * DD + g * LL + tid] = wv;
    }
    // ctx row 0
    if (tid < DD) {
        int h = tid / 12;
        float a = 0.f;
        for (int m = 0; m < len; m++)
            a += sc[h * 68 + m] * g_VN[sn[m] * DD + tid];
        cs[tid] = a;
    }
    __syncthreads();

    // out = ctx @ w_o^T + b_o
    if (tid < DD) {
        float o = b_o[tid];
        #pragma unroll 8
        for (int c = 0; c < DD; c++) o += cs[c] * g_WtO[c * DD + tid];
        out[g * DD + tid] = o;
    }
}

// ---------------- launch ----------------
extern "C" void kernel_launch(void* const* d_in, const int* in_sizes, int n_in,
                              void* d_out, int out_size) {
    const float* x     = (const float*)d_in[0];
    const float* a_l   = (const float*)d_in[1];
    const float* a_r   = (const float*)d_in[2];
    const float* w_ga  = (const float*)d_in[3];
    const float* b_ga  = (const float*)d_in[4];
    const float* w_gb  = (const float*)d_in[5];
    const float* b_gb  = (const float*)d_in[6];
    const float* w_lin = (const float*)d_in[7];
    const float* b_lin = (const float*)d_in[8];
    const float* w_qkv = (const float*)d_in[9];
    const float* b_qkv = (const float*)d_in[10];
    const float* w_o   = (const float*)d_in[11];
    const float* b_o   = (const float*)d_in[12];
    const int*   grph[3] = {(const int*)d_in[13], (const int*)d_in[14], (const int*)d_in[15]};
    const int*   target_ids  = (const int*)d_in[16];
    const int*   target_lens = (const int*)d_in[17];
    float* out = (float*)d_out;

    float *pS, *pA, *pB;
    cudaGetSymbolAddress((void**)&pS, g_S);
    cudaGetSymbolAddress((void**)&pA, g_A);
    cudaGetSymbolAddress((void**)&pB, g_B);
    float* outs[3] = {pS, pA, pB};   // g0->s_out, g1->a_out, g2->b_out

    const int nodeBlocks = (NN + 7) / 8;    // warp per node, 256 thr

    k_transpose<<<(D2 * DD + 255) / 256, 256>>>(w_lin, w_qkv, w_o);
    k_glr1<<<nodeBlocks, 256>>>(x, a_l, a_r);

    for (int i = 0; i < 3; i++) {
        k_zero_deg<<<(NN + 255) / 256, 256>>>();
        k_count<<<(EE + 255) / 256, 256>>>(grph[i]);
        k_scan<<<1, 1024>>>();
        k_fill<<<(EE + 255) / 256, 256>>>(grph[i]);
        k_gather1<<<nodeBlocks, 256>>>(x, a_l + DD, a_r + DD);
        k_gather2<<<nodeBlocks, 256>>>(x, outs[i]);
    }

    k_combine<<<nodeBlocks, 256>>>(x, w_ga, b_ga, w_gb, b_gb);
    k_gemm_h<<<(NN + 31) / 32, DD>>>(b_lin);
    k_gemm_kv<<<(NN + 31) / 32, D2>>>(b_qkv);
    k_attn<<<GG, 128>>>(target_ids, target_lens, b_qkv, b_o, out);
}